// round 13
// baseline (speedup 1.0000x reference)
#include <cuda_runtime.h>
#include <cstdint>

// Problem constants (fixed by the reference)
constexpr int N  = 100000;
constexpr int E  = 1600000;
constexpr int IN = 32;
constexpr int H  = 64;
constexpr int L  = 16;
constexpr int G  = 64;

constexpr int SCAN_CHUNK = 512;
constexpr int NB_SCAN = (N + SCAN_CHUNK - 1) / SCAN_CHUNK;  // 196

#define CDIV(a, b) (((a) + (b) - 1) / (b))

// ---------------- tf32 mma helpers ----------------
__device__ __forceinline__ uint32_t f2tf32(float x) {
    uint32_t r;
    asm("cvt.rna.tf32.f32 %0, %1;" : "=r"(r) : "f"(x));
    return r;
}
__device__ __forceinline__ void mma_tf32(float c[4], uint32_t a0, uint32_t a1,
                                         uint32_t a2, uint32_t a3,
                                         uint32_t b0, uint32_t b1) {
    asm("mma.sync.aligned.m16n8k8.row.col.f32.tf32.tf32.f32 "
        "{%0,%1,%2,%3}, {%4,%5,%6,%7}, {%8,%9}, {%0,%1,%2,%3};"
        : "+f"(c[0]), "+f"(c[1]), "+f"(c[2]), "+f"(c[3])
        : "r"(a0), "r"(a1), "r"(a2), "r"(a3), "r"(b0), "r"(b1));
}

// ---------------- device scratch (no allocations allowed) ----------------
__device__ float g_buf0[N * H];
__device__ float g_buf1[N * H];
__device__ float g_dinv[N];
__device__ int   g_deg[N];
__device__ int   g_rowptr[N + 1];
__device__ int   g_cursor[N];
__device__ int   g_srcs[E];
__device__ int   g_bsum[256];
__device__ float g_pool[G * H];
__device__ float g_cnt[G];

// ---------------- degree histogram: 4 edges/thread ----------------
__global__ void k_hist4(const int4* __restrict__ dst4) {
    int i = blockIdx.x * blockDim.x + threadIdx.x;
    if (i >= E / 4) return;
    int4 d = dst4[i];
    atomicAdd(&g_deg[d.x], 1);
    atomicAdd(&g_deg[d.y], 1);
    atomicAdd(&g_deg[d.z], 1);
    atomicAdd(&g_deg[d.w], 1);
}

// ------- scan pass 1: also computes dinv AND prescales P0 = dinv * x (C=32) -------
__global__ void k_scan1(const float* __restrict__ x, float* __restrict__ P0) {
    __shared__ int s[SCAN_CHUNK];
    int t = threadIdx.x;
    int i = blockIdx.x * SCAN_CHUNK + t;
    int v = (i < N) ? g_deg[i] : 0;
    float d = rsqrtf((float)v + 1.0f);
    if (i < N) g_dinv[i] = d;
    s[t] = v;
    __syncthreads();
#pragma unroll
    for (int off = 1; off < SCAN_CHUNK; off <<= 1) {
        int xx = (t >= off) ? s[t - off] : 0;
        __syncthreads();
        s[t] += xx;
        __syncthreads();
    }
    if (i < N) g_rowptr[i] = s[t] - v;
    if (t == SCAN_CHUNK - 1) g_bsum[blockIdx.x] = s[t];

    // fused prescale: P0 row i = dinv[i] * x[i, :]
    if (i < N) {
        const float4* xv = (const float4*)(x) + (size_t)i * 8;
        float4* ov = (float4*)(P0) + (size_t)i * 8;
#pragma unroll
        for (int k = 0; k < 8; k++) {
            float4 a = xv[k];
            ov[k] = make_float4(a.x * d, a.y * d, a.z * d, a.w * d);
        }
    }
}

// ------- fused scan2+scan3 (also zeroes pool/cnt accumulators) -------
__global__ void k_scan23() {
    __shared__ int s[256];
    __shared__ int excl[256];
    int t = threadIdx.x;
    int v = (t < NB_SCAN) ? g_bsum[t] : 0;
    s[t] = v;
    __syncthreads();
#pragma unroll
    for (int off = 1; off < 256; off <<= 1) {
        int xx = (t >= off) ? s[t - off] : 0;
        __syncthreads();
        s[t] += xx;
        __syncthreads();
    }
    excl[t] = s[t] - v;
    __syncthreads();
    int i = blockIdx.x * blockDim.x + t;
    if (i < N) {
        int r = g_rowptr[i] + excl[i / SCAN_CHUNK];
        g_rowptr[i] = r;
        g_cursor[i] = r;
    }
    if (i == 0) g_rowptr[N] = E;
    // zero pool/cnt (blocks 0..15 cover G*H = 4096; block 16 covers cnt)
    if (blockIdx.x < 16) g_pool[blockIdx.x * 256 + t] = 0.f;
    if (blockIdx.x == 16 && t < G) g_cnt[t] = 0.f;
}

// ---------------- CSR fill: 4 edges/thread ----------------
__global__ void k_fill4(const int4* __restrict__ src4, const int4* __restrict__ dst4) {
    int i = blockIdx.x * blockDim.x + threadIdx.x;
    if (i >= E / 4) return;
    int4 s = src4[i];
    int4 d = dst4[i];
    int p0 = atomicAdd(&g_cursor[d.x], 1);
    int p1 = atomicAdd(&g_cursor[d.y], 1);
    int p2 = atomicAdd(&g_cursor[d.z], 1);
    int p3 = atomicAdd(&g_cursor[d.w], 1);
    g_srcs[p0] = s.x;
    g_srcs[p1] = s.y;
    g_srcs[p2] = s.z;
    g_srcs[p3] = s.w;
}

// =====================================================================
// Warp-per-node CSR gather:
//   32 lanes = EP edges x Q columns (Q = C/4, EP = 32/Q).
//   Each e-slice accumulates edges j = beg+e, beg+e+EP, ...; shfl-xor
//   reduce across e-slices; e==0 lanes add self term + finish.
//   Y[i] = dinv[i] * (sum X[src] + X[i]) (+bias, +relu)
// =====================================================================
template <int C, bool BIAS, bool RELU>
__global__ void k_gather(const float* __restrict__ X, const float* __restrict__ bias,
                         float* __restrict__ Y) {
    constexpr int Q = C / 4;          // column lanes (16 for C=64, 8 for C=32)
    int lane = threadIdx.x & 31;
    int node = (blockIdx.x * blockDim.x + threadIdx.x) >> 5;
    if (node >= N) return;
    int q = lane % Q;                 // column quarter
    int e = lane / Q;                 // edge slice [0, EP)
    int beg = g_rowptr[node];
    int end = g_rowptr[node + 1];
    const float4* Xv = (const float4*)X;
    float4 acc = make_float4(0.f, 0.f, 0.f, 0.f);
    if (e == 0) acc = Xv[(size_t)node * Q + q];   // self term
#pragma unroll 4
    for (int j = beg + e; j < end; j += 32 / Q) {
        int s = g_srcs[j];
        float4 v = Xv[(size_t)s * Q + q];
        acc.x += v.x; acc.y += v.y; acc.z += v.z; acc.w += v.w;
    }
    // reduce across edge slices
#pragma unroll
    for (int off = Q; off < 32; off <<= 1) {
        acc.x += __shfl_xor_sync(0xFFFFFFFFu, acc.x, off);
        acc.y += __shfl_xor_sync(0xFFFFFFFFu, acc.y, off);
        acc.z += __shfl_xor_sync(0xFFFFFFFFu, acc.z, off);
        acc.w += __shfl_xor_sync(0xFFFFFFFFu, acc.w, off);
    }
    if (e != 0) return;
    float d = g_dinv[node];
    acc.x *= d; acc.y *= d; acc.z *= d; acc.w *= d;
    if (BIAS) {
        float4 bv = ((const float4*)bias)[q];
        acc.x += bv.x; acc.y += bv.y; acc.z += bv.z; acc.w += bv.w;
    }
    if (RELU) {
        acc.x = fmaxf(acc.x, 0.f); acc.y = fmaxf(acc.y, 0.f);
        acc.z = fmaxf(acc.z, 0.f); acc.w = fmaxf(acc.w, 0.f);
    }
    ((float4*)Y)[(size_t)node * Q + q] = acc;
}

// =====================================================================
// Tensor-core per-node matmul (tf32 mma.sync, fp32 accumulate).
// Block = 256 threads (8 warps), 128 rows; warp computes 16 rows x COUT.
// =====================================================================
template <int CIN, int COUT, bool SCALE, bool BIAS, bool RELU>
__global__ void __launch_bounds__(256)
k_mmt(const float* __restrict__ X, const float* __restrict__ W,
      const float* __restrict__ bias, float* __restrict__ Y) {
    constexpr int ROWS = 128;
    constexpr int KC = CIN / 8;     // k-chunks
    constexpr int NT = COUT / 8;    // n-tiles
    constexpr int PITCHA = CIN + 4; // bank = 4r+c -> conflict-free fragments
    extern __shared__ char smem_raw[];
    uint32_t* sA = (uint32_t*)smem_raw;                          // ROWS*PITCHA
    float2*   sB = (float2*)(smem_raw + ROWS * PITCHA * 4);      // KC*NT*32

    int t = threadIdx.x;
    int row0 = blockIdx.x * ROWS;

    // stage A (convert to tf32)
    for (int i = t; i < ROWS * CIN / 4; i += 256) {
        int r = i / (CIN / 4), c4 = (i % (CIN / 4)) * 4;
        int row = row0 + r;
        float4 v = (row < N) ? ((const float4*)X)[(size_t)row * (CIN / 4) + c4 / 4]
                             : make_float4(0.f, 0.f, 0.f, 0.f);
        uint32_t* p = sA + r * PITCHA + c4;
        p[0] = f2tf32(v.x); p[1] = f2tf32(v.y);
        p[2] = f2tf32(v.z); p[3] = f2tf32(v.w);
    }
    // stage B in fragment order
    for (int i = t; i < KC * NT * 32; i += 256) {
        int lane = i & 31, tile = i >> 5;
        int kc = tile / NT, nt = tile % NT;
        int kr = kc * 8 + (lane & 3);
        int c  = nt * 8 + (lane >> 2);
        float b0 = W[kr * COUT + c];
        float b1 = W[(kr + 4) * COUT + c];
        sB[i] = make_float2(__uint_as_float(f2tf32(b0)), __uint_as_float(f2tf32(b1)));
    }
    __syncthreads();

    int w = t >> 5, lane = t & 31;
    int r0 = w * 16;
    int lr = lane >> 2, lc = lane & 3;

    float acc[NT][4];
#pragma unroll
    for (int nt = 0; nt < NT; nt++)
#pragma unroll
        for (int j = 0; j < 4; j++) acc[nt][j] = 0.f;

#pragma unroll
    for (int kc = 0; kc < KC; kc++) {
        const uint32_t* base = sA + kc * 8 + lc;
        uint32_t a0 = base[(r0 + lr) * PITCHA];
        uint32_t a1 = base[(r0 + lr + 8) * PITCHA];
        uint32_t a2 = base[(r0 + lr) * PITCHA + 4];
        uint32_t a3 = base[(r0 + lr + 8) * PITCHA + 4];
#pragma unroll
        for (int nt = 0; nt < NT; nt++) {
            float2 b = sB[(kc * NT + nt) * 32 + lane];
            mma_tf32(acc[nt], a0, a1, a2, a3,
                     __float_as_uint(b.x), __float_as_uint(b.y));
        }
    }

    // epilogue
    int ra = row0 + r0 + lr;
    int rb = ra + 8;
    float sa = 1.f, sb = 1.f;
    if (SCALE) {
        if (ra < N) sa = g_dinv[ra];
        if (rb < N) sb = g_dinv[rb];
    }
#pragma unroll
    for (int nt = 0; nt < NT; nt++) {
        int c = nt * 8 + 2 * lc;
        float b0v = 0.f, b1v = 0.f;
        if (BIAS) { b0v = bias[c]; b1v = bias[c + 1]; }
        if (ra < N) {
            float o0 = acc[nt][0] * sa + b0v;
            float o1 = acc[nt][1] * sa + b1v;
            if (RELU) { o0 = fmaxf(o0, 0.f); o1 = fmaxf(o1, 0.f); }
            *(float2*)(Y + (size_t)ra * COUT + c) = make_float2(o0, o1);
        }
        if (rb < N) {
            float o2 = acc[nt][2] * sb + b0v;
            float o3 = acc[nt][3] * sb + b1v;
            if (RELU) { o2 = fmaxf(o2, 0.f); o3 = fmaxf(o3, 0.f); }
            *(float2*)(Y + (size_t)rb * COUT + c) = make_float2(o2, o3);
        }
    }
}

// ---------------- global mean pool (sorted batch, run-length) + counts ----------------
__global__ void k_pool_acc(const int* __restrict__ batch, const float* __restrict__ Hf) {
    int t = threadIdx.x;
    int c = t % 64;
    int base = blockIdx.x * 128;
    float acc = 0.f;
    float cntacc = 0.f;
    int cur = -1;
    for (int j = t / 64; j < 128; j += 4) {
        int i = base + j;
        if (i >= N) break;
        int g = batch[i];
        if (g != cur) {
            if (cur >= 0) {
                atomicAdd(&g_pool[cur * 64 + c], acc);
                if (c == 0) atomicAdd(&g_cnt[cur], cntacc);
            }
            cur = g; acc = 0.f; cntacc = 0.f;
        }
        acc += Hf[(size_t)i * 64 + c];
        cntacc += 1.f;
    }
    if (cur >= 0) {
        atomicAdd(&g_pool[cur * 64 + c], acc);
        if (c == 0) atomicAdd(&g_cnt[cur], cntacc);
    }
}

// ------- decoder broadcast with fused latent projection.
//   smem z = (pool/cnt) @ W_proj + b_proj  (computed per block; block 0 -> out_z)
//   Y = relu(z[batch] @ W_dec_proj + b)    (grid-strided over N*16 float4s)
__global__ void __launch_bounds__(256)
k_dec_bcast(const int* __restrict__ batch,
            const float* __restrict__ Wp, const float* __restrict__ bp,
            const float* __restrict__ Wd, const float* __restrict__ bd,
            float* __restrict__ out_z, float* __restrict__ Y) {
    __shared__ float sz[G * L];
    int t = threadIdx.x;
#pragma unroll
    for (int e = 0; e < (G * L) / 256; e++) {
        int id = t * ((G * L) / 256) + e;
        int g = id / L, l = id % L;
        float inv = 1.0f / fmaxf(g_cnt[g], 1.0f);
        float acc = bp[l];
#pragma unroll
        for (int c = 0; c < H; c++) acc = fmaf(g_pool[g * H + c] * inv, Wp[c * L + l], acc);
        sz[id] = acc;
        if (blockIdx.x == 0) out_z[id] = acc;
    }
    __syncthreads();
    for (int idx = blockIdx.x * 256 + t; idx < N * 16; idx += gridDim.x * 256) {
        int i = idx >> 4, v = idx & 15;
        int gid = batch[i];
        float4 acc = ((const float4*)bd)[v];
#pragma unroll
        for (int l = 0; l < L; l++) {
            float zl = sz[gid * L + l];
            float4 w = ((const float4*)Wd)[l * 16 + v];
            acc.x = fmaf(zl, w.x, acc.x); acc.y = fmaf(zl, w.y, acc.y);
            acc.z = fmaf(zl, w.z, acc.z); acc.w = fmaf(zl, w.w, acc.w);
        }
        acc.x = fmaxf(acc.x, 0.f); acc.y = fmaxf(acc.y, 0.f);
        acc.z = fmaxf(acc.z, 0.f); acc.w = fmaxf(acc.w, 0.f);
        ((float4*)Y)[idx] = acc;
    }
}

// ---------------- launcher ----------------
extern "C" void kernel_launch(void* const* d_in, const int* in_sizes, int n_in,
                              void* d_out, int out_size) {
    const float* x       = (const float*)d_in[0];
    const int*   ei      = (const int*)d_in[1];
    const int*   src     = ei;
    const int*   dst     = ei + E;
    const int*   batch   = (const int*)d_in[2];
    const float* W_enc0  = (const float*)d_in[3];
    const float* b_enc0  = (const float*)d_in[4];
    const float* W_enc1  = (const float*)d_in[5];
    const float* b_enc1  = (const float*)d_in[6];
    const float* W_enc2  = (const float*)d_in[7];
    const float* b_enc2  = (const float*)d_in[8];
    const float* W_proj  = (const float*)d_in[9];
    const float* b_proj  = (const float*)d_in[10];
    const float* W_dproj = (const float*)d_in[11];
    const float* b_dproj = (const float*)d_in[12];
    const float* W_dec0  = (const float*)d_in[13];
    const float* b_dec0  = (const float*)d_in[14];
    const float* W_dec1  = (const float*)d_in[15];
    const float* b_dec1  = (const float*)d_in[16];

    float* out_recon = (float*)d_out;           // [N, IN]
    float* out_z     = (float*)d_out + N * IN;  // [G, L]

    float* buf0;  cudaGetSymbolAddress((void**)&buf0, g_buf0);
    float* buf1;  cudaGetSymbolAddress((void**)&buf1, g_buf1);
    int*   degp;  cudaGetSymbolAddress((void**)&degp, g_deg);

    const int T = 256;

    // dynamic smem: A tile (128 x (CIN+4) u32) + B fragments (KC*NT*32 float2)
    constexpr int SMT_32_64 = 128 * 36 * 4 + (4 * 8 * 32) * 8;   // 26624
    constexpr int SMT_64_64 = 128 * 68 * 4 + (8 * 8 * 32) * 8;   // 51200
    constexpr int SMT_64_32 = 128 * 68 * 4 + (8 * 4 * 32) * 8;   // 43008
    static bool attr_done = false;
    if (!attr_done) {
        cudaFuncSetAttribute((const void*)k_mmt<IN, H, false, true, true>,
                             cudaFuncAttributeMaxDynamicSharedMemorySize, SMT_32_64);
        cudaFuncSetAttribute((const void*)k_mmt<H, H, true, false, false>,
                             cudaFuncAttributeMaxDynamicSharedMemorySize, SMT_64_64);
        cudaFuncSetAttribute((const void*)k_mmt<H, IN, true, false, false>,
                             cudaFuncAttributeMaxDynamicSharedMemorySize, SMT_64_32);
        attr_done = true;
    }

    // ---- CSR build + dinv + prescale (P0 -> buf0)
    cudaMemsetAsync(degp, 0, N * sizeof(int));
    k_hist4<<<CDIV(E / 4, T), T>>>((const int4*)dst);
    k_scan1<<<NB_SCAN, SCAN_CHUNK>>>(x, buf0);
    k_scan23<<<CDIV(N, T), T>>>();
    k_fill4<<<CDIV(E / 4, T), T>>>((const int4*)src, (const int4*)dst);

    const int MMB = CDIV(N, 128);
    const int GWB = CDIV(N * 32, 256);   // warp-per-node gather grid

    // ---- enc0: gather x at C=32, then 32->64 matmul (+bias+relu)
    k_gather<IN, false, false><<<GWB, 256>>>(buf0, nullptr, buf1);
    k_mmt<IN, H, false, true, true><<<MMB, 256, SMT_32_64>>>(buf1, W_enc0, b_enc0, buf0);

    // ---- enc1
    k_mmt<H, H, true, false, false><<<MMB, 256, SMT_64_64>>>(buf0, W_enc1, nullptr, buf1);
    k_gather<H, true, true><<<GWB, 256>>>(buf1, b_enc1, buf0);

    // ---- enc2
    k_mmt<H, H, true, false, false><<<MMB, 256, SMT_64_64>>>(buf0, W_enc2, nullptr, buf1);
    k_gather<H, true, true><<<GWB, 256>>>(buf1, b_enc2, buf0);

    // ---- global mean pool + fused latent projection / decoder broadcast
    k_pool_acc<<<CDIV(N, 128), 256>>>(batch, buf0);
    k_dec_bcast<<<592, 256>>>(batch, W_proj, b_proj, W_dproj, b_dproj, out_z, buf1);

    // ---- dec0
    k_mmt<H, H, true, false, false><<<MMB, 256, SMT_64_64>>>(buf1, W_dec0, nullptr, buf0);
    k_gather<H, true, true><<<GWB, 256>>>(buf0, b_dec0, buf1);

    // ---- dec1: 64->32 matmul (dinv-scaled), gather at C=32 into d_out
    k_mmt<H, IN, true, false, false><<<MMB, 256, SMT_64_32>>>(buf1, W_dec1, nullptr, buf0);
    k_gather<IN, true, false><<<GWB, 256>>>(buf0, b_dec1, out_recon);
}

// round 14
// speedup vs baseline: 1.0586x; 1.0586x over previous
#include <cuda_runtime.h>
#include <cstdint>

// Problem constants (fixed by the reference)
constexpr int N  = 100000;
constexpr int E  = 1600000;
constexpr int IN = 32;
constexpr int H  = 64;
constexpr int L  = 16;
constexpr int G  = 64;

constexpr int SCAN_CHUNK = 512;
constexpr int NB_SCAN = (N + SCAN_CHUNK - 1) / SCAN_CHUNK;  // 196

#define CDIV(a, b) (((a) + (b) - 1) / (b))

// ---------------- tf32 mma helpers ----------------
__device__ __forceinline__ uint32_t f2tf32(float x) {
    uint32_t r;
    asm("cvt.rna.tf32.f32 %0, %1;" : "=r"(r) : "f"(x));
    return r;
}
__device__ __forceinline__ void mma_tf32(float c[4], uint32_t a0, uint32_t a1,
                                         uint32_t a2, uint32_t a3,
                                         uint32_t b0, uint32_t b1) {
    asm("mma.sync.aligned.m16n8k8.row.col.f32.tf32.tf32.f32 "
        "{%0,%1,%2,%3}, {%4,%5,%6,%7}, {%8,%9}, {%0,%1,%2,%3};"
        : "+f"(c[0]), "+f"(c[1]), "+f"(c[2]), "+f"(c[3])
        : "r"(a0), "r"(a1), "r"(a2), "r"(a3), "r"(b0), "r"(b1));
}

// ---------------- device scratch (no allocations allowed) ----------------
__device__ float g_buf0[N * H];
__device__ float g_buf1[N * H];
__device__ float g_dinv[N];
__device__ int   g_deg[N];
__device__ int   g_rowptr[N + 1];
__device__ int   g_cursor[N];
__device__ int   g_srcs[E];
__device__ int   g_bsum[256];
__device__ float g_pool[G * H];
__device__ float g_cnt[G];

// ---------------- degree histogram: 4 edges/thread ----------------
__global__ void k_hist4(const int4* __restrict__ dst4) {
    int i = blockIdx.x * blockDim.x + threadIdx.x;
    if (i >= E / 4) return;
    int4 d = dst4[i];
    atomicAdd(&g_deg[d.x], 1);
    atomicAdd(&g_deg[d.y], 1);
    atomicAdd(&g_deg[d.z], 1);
    atomicAdd(&g_deg[d.w], 1);
}

// ------- scan pass 1: also computes dinv AND prescales P0 = dinv * x (C=32) -------
__global__ void k_scan1(const float* __restrict__ x, float* __restrict__ P0) {
    __shared__ int s[SCAN_CHUNK];
    int t = threadIdx.x;
    int i = blockIdx.x * SCAN_CHUNK + t;
    int v = (i < N) ? g_deg[i] : 0;
    float d = rsqrtf((float)v + 1.0f);
    if (i < N) g_dinv[i] = d;
    s[t] = v;
    __syncthreads();
#pragma unroll
    for (int off = 1; off < SCAN_CHUNK; off <<= 1) {
        int xx = (t >= off) ? s[t - off] : 0;
        __syncthreads();
        s[t] += xx;
        __syncthreads();
    }
    if (i < N) g_rowptr[i] = s[t] - v;
    if (t == SCAN_CHUNK - 1) g_bsum[blockIdx.x] = s[t];

    // fused prescale: P0 row i = dinv[i] * x[i, :]
    if (i < N) {
        const float4* xv = (const float4*)(x) + (size_t)i * 8;
        float4* ov = (float4*)(P0) + (size_t)i * 8;
#pragma unroll
        for (int k = 0; k < 8; k++) {
            float4 a = xv[k];
            ov[k] = make_float4(a.x * d, a.y * d, a.z * d, a.w * d);
        }
    }
}

// ------- fused scan2+scan3 (also zeroes pool/cnt accumulators) -------
__global__ void k_scan23() {
    __shared__ int s[256];
    __shared__ int excl[256];
    int t = threadIdx.x;
    int v = (t < NB_SCAN) ? g_bsum[t] : 0;
    s[t] = v;
    __syncthreads();
#pragma unroll
    for (int off = 1; off < 256; off <<= 1) {
        int xx = (t >= off) ? s[t - off] : 0;
        __syncthreads();
        s[t] += xx;
        __syncthreads();
    }
    excl[t] = s[t] - v;
    __syncthreads();
    int i = blockIdx.x * blockDim.x + t;
    if (i < N) {
        int r = g_rowptr[i] + excl[i / SCAN_CHUNK];
        g_rowptr[i] = r;
        g_cursor[i] = r;
    }
    if (i == 0) g_rowptr[N] = E;
    // zero pool/cnt (blocks 0..15 cover G*H = 4096; block 16 covers cnt)
    if (blockIdx.x < 16) g_pool[blockIdx.x * 256 + t] = 0.f;
    if (blockIdx.x == 16 && t < G) g_cnt[t] = 0.f;
}

// ---------------- CSR fill: 4 edges/thread ----------------
__global__ void k_fill4(const int4* __restrict__ src4, const int4* __restrict__ dst4) {
    int i = blockIdx.x * blockDim.x + threadIdx.x;
    if (i >= E / 4) return;
    int4 s = src4[i];
    int4 d = dst4[i];
    int p0 = atomicAdd(&g_cursor[d.x], 1);
    int p1 = atomicAdd(&g_cursor[d.y], 1);
    int p2 = atomicAdd(&g_cursor[d.z], 1);
    int p3 = atomicAdd(&g_cursor[d.w], 1);
    g_srcs[p0] = s.x;
    g_srcs[p1] = s.y;
    g_srcs[p2] = s.z;
    g_srcs[p3] = s.w;
}

// ---------------- CSR gather (R8 layout):  Y[i] = dinv[i]*(sum X[s] + X[i]) ----------------
template <int C, bool BIAS, bool RELU>
__global__ void k_gather(const float* __restrict__ X, const float* __restrict__ bias,
                         float* __restrict__ Y) {
    constexpr int Q = C / 4;
    constexpr int NPB = 256 / Q;
    int t = threadIdx.x;
    int node = blockIdx.x * NPB + t / Q;
    int q = t % Q;
    if (node >= N) return;
    int beg = g_rowptr[node];
    int end = g_rowptr[node + 1];
    const float4* Xv = (const float4*)X;
    float4 acc = Xv[(size_t)node * Q + q];
#pragma unroll 4
    for (int j = beg; j < end; j++) {
        int s = g_srcs[j];
        float4 v = Xv[(size_t)s * Q + q];
        acc.x += v.x; acc.y += v.y; acc.z += v.z; acc.w += v.w;
    }
    float d = g_dinv[node];
    acc.x *= d; acc.y *= d; acc.z *= d; acc.w *= d;
    if (BIAS) {
        float4 bv = ((const float4*)bias)[q];
        acc.x += bv.x; acc.y += bv.y; acc.z += bv.z; acc.w += bv.w;
    }
    if (RELU) {
        acc.x = fmaxf(acc.x, 0.f); acc.y = fmaxf(acc.y, 0.f);
        acc.z = fmaxf(acc.z, 0.f); acc.w = fmaxf(acc.w, 0.f);
    }
    ((float4*)Y)[(size_t)node * Q + q] = acc;
}

// =====================================================================
// Tensor-core per-node matmul (tf32 mma.sync, fp32 accumulate).
// Block = 256 threads (8 warps), 128 rows; warp computes 16 rows x COUT.
// =====================================================================
template <int CIN, int COUT, bool SCALE, bool BIAS, bool RELU>
__global__ void __launch_bounds__(256)
k_mmt(const float* __restrict__ X, const float* __restrict__ W,
      const float* __restrict__ bias, float* __restrict__ Y) {
    constexpr int ROWS = 128;
    constexpr int KC = CIN / 8;     // k-chunks
    constexpr int NT = COUT / 8;    // n-tiles
    constexpr int PITCHA = CIN + 4; // bank = 4r+c -> conflict-free fragments
    extern __shared__ char smem_raw[];
    uint32_t* sA = (uint32_t*)smem_raw;                          // ROWS*PITCHA
    float2*   sB = (float2*)(smem_raw + ROWS * PITCHA * 4);      // KC*NT*32

    int t = threadIdx.x;
    int row0 = blockIdx.x * ROWS;

    // stage A (convert to tf32)
    for (int i = t; i < ROWS * CIN / 4; i += 256) {
        int r = i / (CIN / 4), c4 = (i % (CIN / 4)) * 4;
        int row = row0 + r;
        float4 v = (row < N) ? ((const float4*)X)[(size_t)row * (CIN / 4) + c4 / 4]
                             : make_float4(0.f, 0.f, 0.f, 0.f);
        uint32_t* p = sA + r * PITCHA + c4;
        p[0] = f2tf32(v.x); p[1] = f2tf32(v.y);
        p[2] = f2tf32(v.z); p[3] = f2tf32(v.w);
    }
    // stage B in fragment order
    for (int i = t; i < KC * NT * 32; i += 256) {
        int lane = i & 31, tile = i >> 5;
        int kc = tile / NT, nt = tile % NT;
        int kr = kc * 8 + (lane & 3);
        int c  = nt * 8 + (lane >> 2);
        float b0 = W[kr * COUT + c];
        float b1 = W[(kr + 4) * COUT + c];
        sB[i] = make_float2(__uint_as_float(f2tf32(b0)), __uint_as_float(f2tf32(b1)));
    }
    __syncthreads();

    int w = t >> 5, lane = t & 31;
    int r0 = w * 16;
    int lr = lane >> 2, lc = lane & 3;

    float acc[NT][4];
#pragma unroll
    for (int nt = 0; nt < NT; nt++)
#pragma unroll
        for (int j = 0; j < 4; j++) acc[nt][j] = 0.f;

#pragma unroll
    for (int kc = 0; kc < KC; kc++) {
        const uint32_t* base = sA + kc * 8 + lc;
        uint32_t a0 = base[(r0 + lr) * PITCHA];
        uint32_t a1 = base[(r0 + lr + 8) * PITCHA];
        uint32_t a2 = base[(r0 + lr) * PITCHA + 4];
        uint32_t a3 = base[(r0 + lr + 8) * PITCHA + 4];
#pragma unroll
        for (int nt = 0; nt < NT; nt++) {
            float2 b = sB[(kc * NT + nt) * 32 + lane];
            mma_tf32(acc[nt], a0, a1, a2, a3,
                     __float_as_uint(b.x), __float_as_uint(b.y));
        }
    }

    // epilogue
    int ra = row0 + r0 + lr;
    int rb = ra + 8;
    float sa = 1.f, sb = 1.f;
    if (SCALE) {
        if (ra < N) sa = g_dinv[ra];
        if (rb < N) sb = g_dinv[rb];
    }
#pragma unroll
    for (int nt = 0; nt < NT; nt++) {
        int c = nt * 8 + 2 * lc;
        float b0v = 0.f, b1v = 0.f;
        if (BIAS) { b0v = bias[c]; b1v = bias[c + 1]; }
        if (ra < N) {
            float o0 = acc[nt][0] * sa + b0v;
            float o1 = acc[nt][1] * sa + b1v;
            if (RELU) { o0 = fmaxf(o0, 0.f); o1 = fmaxf(o1, 0.f); }
            *(float2*)(Y + (size_t)ra * COUT + c) = make_float2(o0, o1);
        }
        if (rb < N) {
            float o2 = acc[nt][2] * sb + b0v;
            float o3 = acc[nt][3] * sb + b1v;
            if (RELU) { o2 = fmaxf(o2, 0.f); o3 = fmaxf(o3, 0.f); }
            *(float2*)(Y + (size_t)rb * COUT + c) = make_float2(o2, o3);
        }
    }
}

// ---------------- global mean pool (sorted batch, run-length) + counts ----------------
__global__ void k_pool_acc(const int* __restrict__ batch, const float* __restrict__ Hf) {
    int t = threadIdx.x;
    int c = t % 64;
    int base = blockIdx.x * 128;
    float acc = 0.f;
    float cntacc = 0.f;
    int cur = -1;
    for (int j = t / 64; j < 128; j += 4) {
        int i = base + j;
        if (i >= N) break;
        int g = batch[i];
        if (g != cur) {
            if (cur >= 0) {
                atomicAdd(&g_pool[cur * 64 + c], acc);
                if (c == 0) atomicAdd(&g_cnt[cur], cntacc);
            }
            cur = g; acc = 0.f; cntacc = 0.f;
        }
        acc += Hf[(size_t)i * 64 + c];
        cntacc += 1.f;
    }
    if (cur >= 0) {
        atomicAdd(&g_pool[cur * 64 + c], acc);
        if (c == 0) atomicAdd(&g_cnt[cur], cntacc);
    }
}

// ------- decoder broadcast with fused latent projection.
//   smem z = (pool/cnt) @ W_proj + b_proj  (computed per block; block 0 -> out_z)
//   Y = relu(z[batch] @ W_dec_proj + b)    (grid-strided over N*16 float4s)
__global__ void __launch_bounds__(256)
k_dec_bcast(const int* __restrict__ batch,
            const float* __restrict__ Wp, const float* __restrict__ bp,
            const float* __restrict__ Wd, const float* __restrict__ bd,
            float* __restrict__ out_z, float* __restrict__ Y) {
    __shared__ float sz[G * L];
    int t = threadIdx.x;
#pragma unroll
    for (int e = 0; e < (G * L) / 256; e++) {
        int id = t * ((G * L) / 256) + e;
        int g = id / L, l = id % L;
        float inv = 1.0f / fmaxf(g_cnt[g], 1.0f);
        float acc = bp[l];
#pragma unroll
        for (int c = 0; c < H; c++) acc = fmaf(g_pool[g * H + c] * inv, Wp[c * L + l], acc);
        sz[id] = acc;
        if (blockIdx.x == 0) out_z[id] = acc;
    }
    __syncthreads();
    for (int idx = blockIdx.x * 256 + t; idx < N * 16; idx += gridDim.x * 256) {
        int i = idx >> 4, v = idx & 15;
        int gid = batch[i];
        float4 acc = ((const float4*)bd)[v];
#pragma unroll
        for (int l = 0; l < L; l++) {
            float zl = sz[gid * L + l];
            float4 w = ((const float4*)Wd)[l * 16 + v];
            acc.x = fmaf(zl, w.x, acc.x); acc.y = fmaf(zl, w.y, acc.y);
            acc.z = fmaf(zl, w.z, acc.z); acc.w = fmaf(zl, w.w, acc.w);
        }
        acc.x = fmaxf(acc.x, 0.f); acc.y = fmaxf(acc.y, 0.f);
        acc.z = fmaxf(acc.z, 0.f); acc.w = fmaxf(acc.w, 0.f);
        ((float4*)Y)[idx] = acc;
    }
}

// ---------------- launcher ----------------
extern "C" void kernel_launch(void* const* d_in, const int* in_sizes, int n_in,
                              void* d_out, int out_size) {
    const float* x       = (const float*)d_in[0];
    const int*   ei      = (const int*)d_in[1];
    const int*   src     = ei;
    const int*   dst     = ei + E;
    const int*   batch   = (const int*)d_in[2];
    const float* W_enc0  = (const float*)d_in[3];
    const float* b_enc0  = (const float*)d_in[4];
    const float* W_enc1  = (const float*)d_in[5];
    const float* b_enc1  = (const float*)d_in[6];
    const float* W_enc2  = (const float*)d_in[7];
    const float* b_enc2  = (const float*)d_in[8];
    const float* W_proj  = (const float*)d_in[9];
    const float* b_proj  = (const float*)d_in[10];
    const float* W_dproj = (const float*)d_in[11];
    const float* b_dproj = (const float*)d_in[12];
    const float* W_dec0  = (const float*)d_in[13];
    const float* b_dec0  = (const float*)d_in[14];
    const float* W_dec1  = (const float*)d_in[15];
    const float* b_dec1  = (const float*)d_in[16];

    float* out_recon = (float*)d_out;           // [N, IN]
    float* out_z     = (float*)d_out + N * IN;  // [G, L]

    float* buf0;  cudaGetSymbolAddress((void**)&buf0, g_buf0);
    float* buf1;  cudaGetSymbolAddress((void**)&buf1, g_buf1);
    int*   degp;  cudaGetSymbolAddress((void**)&degp, g_deg);

    const int T = 256;

    // dynamic smem: A tile (128 x (CIN+4) u32) + B fragments (KC*NT*32 float2)
    constexpr int SMT_32_64 = 128 * 36 * 4 + (4 * 8 * 32) * 8;   // 26624
    constexpr int SMT_64_64 = 128 * 68 * 4 + (8 * 8 * 32) * 8;   // 51200
    constexpr int SMT_64_32 = 128 * 68 * 4 + (8 * 4 * 32) * 8;   // 43008
    static bool attr_done = false;
    if (!attr_done) {
        cudaFuncSetAttribute((const void*)k_mmt<IN, H, false, true, true>,
                             cudaFuncAttributeMaxDynamicSharedMemorySize, SMT_32_64);
        cudaFuncSetAttribute((const void*)k_mmt<H, H, true, false, false>,
                             cudaFuncAttributeMaxDynamicSharedMemorySize, SMT_64_64);
        cudaFuncSetAttribute((const void*)k_mmt<H, IN, true, false, false>,
                             cudaFuncAttributeMaxDynamicSharedMemorySize, SMT_64_32);
        attr_done = true;
    }

    // ---- CSR build + dinv + fused prescale (P0 -> buf0)
    cudaMemsetAsync(degp, 0, N * sizeof(int));
    k_hist4<<<CDIV(E / 4, T), T>>>((const int4*)dst);
    k_scan1<<<NB_SCAN, SCAN_CHUNK>>>(x, buf0);
    k_scan23<<<CDIV(N, T), T>>>();
    k_fill4<<<CDIV(E / 4, T), T>>>((const int4*)src, (const int4*)dst);

    const int MMB = CDIV(N, 128);

    // ---- enc0: gather x at C=32, then 32->64 matmul (+bias+relu)
    k_gather<IN, false, false><<<CDIV(N, 32), 256>>>(buf0, nullptr, buf1);
    k_mmt<IN, H, false, true, true><<<MMB, 256, SMT_32_64>>>(buf1, W_enc0, b_enc0, buf0);

    // ---- enc1
    k_mmt<H, H, true, false, false><<<MMB, 256, SMT_64_64>>>(buf0, W_enc1, nullptr, buf1);
    k_gather<H, true, true><<<CDIV(N, 16), 256>>>(buf1, b_enc1, buf0);

    // ---- enc2
    k_mmt<H, H, true, false, false><<<MMB, 256, SMT_64_64>>>(buf0, W_enc2, nullptr, buf1);
    k_gather<H, true, true><<<CDIV(N, 16), 256>>>(buf1, b_enc2, buf0);

    // ---- global mean pool + fused latent projection / decoder broadcast
    k_pool_acc<<<CDIV(N, 128), 256>>>(batch, buf0);
    k_dec_bcast<<<592, 256>>>(batch, W_proj, b_proj, W_dproj, b_dproj, out_z, buf1);

    // ---- dec0
    k_mmt<H, H, true, false, false><<<MMB, 256, SMT_64_64>>>(buf1, W_dec0, nullptr, buf0);
    k_gather<H, true, true><<<CDIV(N, 16), 256>>>(buf0, b_dec0, buf1);

    // ---- dec1: 64->32 matmul (dinv-scaled), gather at C=32 into d_out
    k_mmt<H, IN, true, false, false><<<MMB, 256, SMT_64_32>>>(buf1, W_dec1, nullptr, buf0);
    k_gather<IN, true, false><<<CDIV(N, 32), 256>>>(buf0, b_dec1, out_recon);
}

// round 15
// speedup vs baseline: 1.1545x; 1.0906x over previous
#include <cuda_runtime.h>
#include <cstdint>

// Problem constants (fixed by the reference)
constexpr int N  = 100000;
constexpr int E  = 1600000;
constexpr int IN = 32;
constexpr int H  = 64;
constexpr int L  = 16;
constexpr int G  = 64;

constexpr int SCAN_CHUNK = 512;
constexpr int NB_SCAN = (N + SCAN_CHUNK - 1) / SCAN_CHUNK;  // 196

#define CDIV(a, b) (((a) + (b) - 1) / (b))

// ---------------- tf32 mma helpers ----------------
__device__ __forceinline__ uint32_t f2tf32(float x) {
    uint32_t r;
    asm("cvt.rna.tf32.f32 %0, %1;" : "=r"(r) : "f"(x));
    return r;
}
__device__ __forceinline__ void mma_tf32(float c[4], uint32_t a0, uint32_t a1,
                                         uint32_t a2, uint32_t a3,
                                         uint32_t b0, uint32_t b1) {
    asm("mma.sync.aligned.m16n8k8.row.col.f32.tf32.tf32.f32 "
        "{%0,%1,%2,%3}, {%4,%5,%6,%7}, {%8,%9}, {%0,%1,%2,%3};"
        : "+f"(c[0]), "+f"(c[1]), "+f"(c[2]), "+f"(c[3])
        : "r"(a0), "r"(a1), "r"(a2), "r"(a3), "r"(b0), "r"(b1));
}

// ---------------- device scratch (no allocations allowed) ----------------
__device__ float g_buf0[N * H];
__device__ float g_buf1[N * H];
__device__ float g_dinv[N];
__device__ int   g_deg[N];
__device__ int   g_rowptr[N + 1];
__device__ int   g_cursor[N];
__device__ int   g_srcs[E];
__device__ int   g_bsum[256];
__device__ float g_pool[G * H];
__device__ float g_cnt[G];
__device__ float g_z[G * L];

// ---------------- degree histogram: 4 edges/thread ----------------
__global__ void k_hist4(const int4* __restrict__ dst4) {
    int i = blockIdx.x * blockDim.x + threadIdx.x;
    if (i >= E / 4) return;
    int4 d = dst4[i];
    atomicAdd(&g_deg[d.x], 1);
    atomicAdd(&g_deg[d.y], 1);
    atomicAdd(&g_deg[d.z], 1);
    atomicAdd(&g_deg[d.w], 1);
}

// ------- scan pass 1: computes dinv AND prescales P0 = dinv * x (C=32) -------
__global__ void k_scan1(const float* __restrict__ x, float* __restrict__ P0) {
    __shared__ int s[SCAN_CHUNK];
    int t = threadIdx.x;
    int i = blockIdx.x * SCAN_CHUNK + t;
    int v = (i < N) ? g_deg[i] : 0;
    float d = rsqrtf((float)v + 1.0f);
    if (i < N) g_dinv[i] = d;
    s[t] = v;
    __syncthreads();
#pragma unroll
    for (int off = 1; off < SCAN_CHUNK; off <<= 1) {
        int xx = (t >= off) ? s[t - off] : 0;
        __syncthreads();
        s[t] += xx;
        __syncthreads();
    }
    if (i < N) g_rowptr[i] = s[t] - v;
    if (t == SCAN_CHUNK - 1) g_bsum[blockIdx.x] = s[t];

    // fused prescale: P0 row i = dinv[i] * x[i, :]
    if (i < N) {
        const float4* xv = (const float4*)(x) + (size_t)i * 8;
        float4* ov = (float4*)(P0) + (size_t)i * 8;
#pragma unroll
        for (int k = 0; k < 8; k++) {
            float4 a = xv[k];
            ov[k] = make_float4(a.x * d, a.y * d, a.z * d, a.w * d);
        }
    }
}

// ------- fused scan2+scan3 (also zeroes pool/cnt accumulators) -------
__global__ void k_scan23() {
    __shared__ int s[256];
    __shared__ int excl[256];
    int t = threadIdx.x;
    int v = (t < NB_SCAN) ? g_bsum[t] : 0;
    s[t] = v;
    __syncthreads();
#pragma unroll
    for (int off = 1; off < 256; off <<= 1) {
        int xx = (t >= off) ? s[t - off] : 0;
        __syncthreads();
        s[t] += xx;
        __syncthreads();
    }
    excl[t] = s[t] - v;
    __syncthreads();
    int i = blockIdx.x * blockDim.x + t;
    if (i < N) {
        int r = g_rowptr[i] + excl[i / SCAN_CHUNK];
        g_rowptr[i] = r;
        g_cursor[i] = r;
    }
    if (i == 0) g_rowptr[N] = E;
    // zero pool/cnt (blocks 0..15 cover G*H = 4096; block 16 covers cnt)
    if (blockIdx.x < 16) g_pool[blockIdx.x * 256 + t] = 0.f;
    if (blockIdx.x == 16 && t < G) g_cnt[t] = 0.f;
}

// ---------------- CSR fill: 4 edges/thread ----------------
__global__ void k_fill4(const int4* __restrict__ src4, const int4* __restrict__ dst4) {
    int i = blockIdx.x * blockDim.x + threadIdx.x;
    if (i >= E / 4) return;
    int4 s = src4[i];
    int4 d = dst4[i];
    int p0 = atomicAdd(&g_cursor[d.x], 1);
    int p1 = atomicAdd(&g_cursor[d.y], 1);
    int p2 = atomicAdd(&g_cursor[d.z], 1);
    int p3 = atomicAdd(&g_cursor[d.w], 1);
    g_srcs[p0] = s.x;
    g_srcs[p1] = s.y;
    g_srcs[p2] = s.z;
    g_srcs[p3] = s.w;
}

// ---------------- CSR gather (R8 layout):  Y[i] = dinv[i]*(sum X[s] + X[i]) ----------------
template <int C, bool BIAS, bool RELU>
__global__ void k_gather(const float* __restrict__ X, const float* __restrict__ bias,
                         float* __restrict__ Y) {
    constexpr int Q = C / 4;
    constexpr int NPB = 256 / Q;
    int t = threadIdx.x;
    int node = blockIdx.x * NPB + t / Q;
    int q = t % Q;
    if (node >= N) return;
    int beg = g_rowptr[node];
    int end = g_rowptr[node + 1];
    const float4* Xv = (const float4*)X;
    float4 acc = Xv[(size_t)node * Q + q];
#pragma unroll 4
    for (int j = beg; j < end; j++) {
        int s = g_srcs[j];
        float4 v = Xv[(size_t)s * Q + q];
        acc.x += v.x; acc.y += v.y; acc.z += v.z; acc.w += v.w;
    }
    float d = g_dinv[node];
    acc.x *= d; acc.y *= d; acc.z *= d; acc.w *= d;
    if (BIAS) {
        float4 bv = ((const float4*)bias)[q];
        acc.x += bv.x; acc.y += bv.y; acc.z += bv.z; acc.w += bv.w;
    }
    if (RELU) {
        acc.x = fmaxf(acc.x, 0.f); acc.y = fmaxf(acc.y, 0.f);
        acc.z = fmaxf(acc.z, 0.f); acc.w = fmaxf(acc.w, 0.f);
    }
    ((float4*)Y)[(size_t)node * Q + q] = acc;
}

// =====================================================================
// Tensor-core per-node matmul (tf32 mma.sync, fp32 accumulate).
// Block = 256 threads (8 warps), 128 rows; warp computes 16 rows x COUT.
// =====================================================================
template <int CIN, int COUT, bool SCALE, bool BIAS, bool RELU>
__global__ void __launch_bounds__(256)
k_mmt(const float* __restrict__ X, const float* __restrict__ W,
      const float* __restrict__ bias, float* __restrict__ Y) {
    constexpr int ROWS = 128;
    constexpr int KC = CIN / 8;     // k-chunks
    constexpr int NT = COUT / 8;    // n-tiles
    constexpr int PITCHA = CIN + 4; // bank = 4r+c -> conflict-free fragments
    extern __shared__ char smem_raw[];
    uint32_t* sA = (uint32_t*)smem_raw;                          // ROWS*PITCHA
    float2*   sB = (float2*)(smem_raw + ROWS * PITCHA * 4);      // KC*NT*32

    int t = threadIdx.x;
    int row0 = blockIdx.x * ROWS;

    // stage A (convert to tf32)
    for (int i = t; i < ROWS * CIN / 4; i += 256) {
        int r = i / (CIN / 4), c4 = (i % (CIN / 4)) * 4;
        int row = row0 + r;
        float4 v = (row < N) ? ((const float4*)X)[(size_t)row * (CIN / 4) + c4 / 4]
                             : make_float4(0.f, 0.f, 0.f, 0.f);
        uint32_t* p = sA + r * PITCHA + c4;
        p[0] = f2tf32(v.x); p[1] = f2tf32(v.y);
        p[2] = f2tf32(v.z); p[3] = f2tf32(v.w);
    }
    // stage B in fragment order
    for (int i = t; i < KC * NT * 32; i += 256) {
        int lane = i & 31, tile = i >> 5;
        int kc = tile / NT, nt = tile % NT;
        int kr = kc * 8 + (lane & 3);
        int c  = nt * 8 + (lane >> 2);
        float b0 = W[kr * COUT + c];
        float b1 = W[(kr + 4) * COUT + c];
        sB[i] = make_float2(__uint_as_float(f2tf32(b0)), __uint_as_float(f2tf32(b1)));
    }
    __syncthreads();

    int w = t >> 5, lane = t & 31;
    int r0 = w * 16;
    int lr = lane >> 2, lc = lane & 3;

    float acc[NT][4];
#pragma unroll
    for (int nt = 0; nt < NT; nt++)
#pragma unroll
        for (int j = 0; j < 4; j++) acc[nt][j] = 0.f;

#pragma unroll
    for (int kc = 0; kc < KC; kc++) {
        const uint32_t* base = sA + kc * 8 + lc;
        uint32_t a0 = base[(r0 + lr) * PITCHA];
        uint32_t a1 = base[(r0 + lr + 8) * PITCHA];
        uint32_t a2 = base[(r0 + lr) * PITCHA + 4];
        uint32_t a3 = base[(r0 + lr + 8) * PITCHA + 4];
#pragma unroll
        for (int nt = 0; nt < NT; nt++) {
            float2 b = sB[(kc * NT + nt) * 32 + lane];
            mma_tf32(acc[nt], a0, a1, a2, a3,
                     __float_as_uint(b.x), __float_as_uint(b.y));
        }
    }

    // epilogue
    int ra = row0 + r0 + lr;
    int rb = ra + 8;
    float sa = 1.f, sb = 1.f;
    if (SCALE) {
        if (ra < N) sa = g_dinv[ra];
        if (rb < N) sb = g_dinv[rb];
    }
#pragma unroll
    for (int nt = 0; nt < NT; nt++) {
        int c = nt * 8 + 2 * lc;
        float b0v = 0.f, b1v = 0.f;
        if (BIAS) { b0v = bias[c]; b1v = bias[c + 1]; }
        if (ra < N) {
            float o0 = acc[nt][0] * sa + b0v;
            float o1 = acc[nt][1] * sa + b1v;
            if (RELU) { o0 = fmaxf(o0, 0.f); o1 = fmaxf(o1, 0.f); }
            *(float2*)(Y + (size_t)ra * COUT + c) = make_float2(o0, o1);
        }
        if (rb < N) {
            float o2 = acc[nt][2] * sb + b0v;
            float o3 = acc[nt][3] * sb + b1v;
            if (RELU) { o2 = fmaxf(o2, 0.f); o3 = fmaxf(o3, 0.f); }
            *(float2*)(Y + (size_t)rb * COUT + c) = make_float2(o2, o3);
        }
    }
}

// ---------------- global mean pool (sorted batch, run-length) + counts ----------------
__global__ void k_pool_acc(const int* __restrict__ batch, const float* __restrict__ Hf) {
    int t = threadIdx.x;
    int c = t % 64;
    int base = blockIdx.x * 128;
    float acc = 0.f;
    float cntacc = 0.f;
    int cur = -1;
    for (int j = t / 64; j < 128; j += 4) {
        int i = base + j;
        if (i >= N) break;
        int g = batch[i];
        if (g != cur) {
            if (cur >= 0) {
                atomicAdd(&g_pool[cur * 64 + c], acc);
                if (c == 0) atomicAdd(&g_cnt[cur], cntacc);
            }
            cur = g; acc = 0.f; cntacc = 0.f;
        }
        acc += Hf[(size_t)i * 64 + c];
        cntacc += 1.f;
    }
    if (cur >= 0) {
        atomicAdd(&g_pool[cur * 64 + c], acc);
        if (c == 0) atomicAdd(&g_cnt[cur], cntacc);
    }
}

// ---------------- latent projection: z = mean @ W_proj + b  (single block) ----------------
__global__ void k_z(const float* __restrict__ Wp, const float* __restrict__ bp,
                    float* __restrict__ out_z) {
    int t = threadIdx.x;  // 1024 = G*L
    int g = t / L, l = t % L;
    float inv = 1.0f / fmaxf(g_cnt[g], 1.0f);
    float acc = bp[l];
#pragma unroll
    for (int c = 0; c < H; c++) acc = fmaf(g_pool[g * H + c] * inv, Wp[c * L + l], acc);
    g_z[t] = acc;
    out_z[t] = acc;
}

// ------- decoder broadcast: h_d = relu(z[batch] @ W_dec_proj + b) -------
__global__ void k_dec_bcast(const int* __restrict__ batch, const float* __restrict__ W,
                            const float* __restrict__ b, float* __restrict__ Y) {
    int idx = blockIdx.x * blockDim.x + threadIdx.x;  // N * 16
    if (idx >= N * 16) return;
    int i = idx >> 4, v = idx & 15;
    int gid = batch[i];
    float4 acc = ((const float4*)b)[v];
#pragma unroll
    for (int l = 0; l < L; l++) {
        float zl = g_z[gid * L + l];
        float4 w = ((const float4*)W)[l * 16 + v];
        acc.x = fmaf(zl, w.x, acc.x); acc.y = fmaf(zl, w.y, acc.y);
        acc.z = fmaf(zl, w.z, acc.z); acc.w = fmaf(zl, w.w, acc.w);
    }
    acc.x = fmaxf(acc.x, 0.f); acc.y = fmaxf(acc.y, 0.f);
    acc.z = fmaxf(acc.z, 0.f); acc.w = fmaxf(acc.w, 0.f);
    ((float4*)Y)[idx] = acc;
}

// ---------------- launcher ----------------
extern "C" void kernel_launch(void* const* d_in, const int* in_sizes, int n_in,
                              void* d_out, int out_size) {
    const float* x       = (const float*)d_in[0];
    const int*   ei      = (const int*)d_in[1];
    const int*   src     = ei;
    const int*   dst     = ei + E;
    const int*   batch   = (const int*)d_in[2];
    const float* W_enc0  = (const float*)d_in[3];
    const float* b_enc0  = (const float*)d_in[4];
    const float* W_enc1  = (const float*)d_in[5];
    const float* b_enc1  = (const float*)d_in[6];
    const float* W_enc2  = (const float*)d_in[7];
    const float* b_enc2  = (const float*)d_in[8];
    const float* W_proj  = (const float*)d_in[9];
    const float* b_proj  = (const float*)d_in[10];
    const float* W_dproj = (const float*)d_in[11];
    const float* b_dproj = (const float*)d_in[12];
    const float* W_dec0  = (const float*)d_in[13];
    const float* b_dec0  = (const float*)d_in[14];
    const float* W_dec1  = (const float*)d_in[15];
    const float* b_dec1  = (const float*)d_in[16];

    float* out_recon = (float*)d_out;           // [N, IN]
    float* out_z     = (float*)d_out + N * IN;  // [G, L]

    float* buf0;  cudaGetSymbolAddress((void**)&buf0, g_buf0);
    float* buf1;  cudaGetSymbolAddress((void**)&buf1, g_buf1);
    int*   degp;  cudaGetSymbolAddress((void**)&degp, g_deg);

    const int T = 256;

    // dynamic smem: A tile (128 x (CIN+4) u32) + B fragments (KC*NT*32 float2)
    constexpr int SMT_32_64 = 128 * 36 * 4 + (4 * 8 * 32) * 8;   // 26624
    constexpr int SMT_64_64 = 128 * 68 * 4 + (8 * 8 * 32) * 8;   // 51200
    constexpr int SMT_64_32 = 128 * 68 * 4 + (8 * 4 * 32) * 8;   // 43008
    static bool attr_done = false;
    if (!attr_done) {
        cudaFuncSetAttribute((const void*)k_mmt<IN, H, false, true, true>,
                             cudaFuncAttributeMaxDynamicSharedMemorySize, SMT_32_64);
        cudaFuncSetAttribute((const void*)k_mmt<H, H, true, false, false>,
                             cudaFuncAttributeMaxDynamicSharedMemorySize, SMT_64_64);
        cudaFuncSetAttribute((const void*)k_mmt<H, IN, true, false, false>,
                             cudaFuncAttributeMaxDynamicSharedMemorySize, SMT_64_32);
        attr_done = true;
    }

    // ---- CSR build + dinv + fused prescale (P0 -> buf0)
    cudaMemsetAsync(degp, 0, N * sizeof(int));
    k_hist4<<<CDIV(E / 4, T), T>>>((const int4*)dst);
    k_scan1<<<NB_SCAN, SCAN_CHUNK>>>(x, buf0);
    k_scan23<<<CDIV(N, T), T>>>();
    k_fill4<<<CDIV(E / 4, T), T>>>((const int4*)src, (const int4*)dst);

    const int MMB = CDIV(N, 128);

    // ---- enc0: gather x at C=32, then 32->64 matmul (+bias+relu)
    k_gather<IN, false, false><<<CDIV(N, 32), 256>>>(buf0, nullptr, buf1);
    k_mmt<IN, H, false, true, true><<<MMB, 256, SMT_32_64>>>(buf1, W_enc0, b_enc0, buf0);

    // ---- enc1
    k_mmt<H, H, true, false, false><<<MMB, 256, SMT_64_64>>>(buf0, W_enc1, nullptr, buf1);
    k_gather<H, true, true><<<CDIV(N, 16), 256>>>(buf1, b_enc1, buf0);

    // ---- enc2
    k_mmt<H, H, true, false, false><<<MMB, 256, SMT_64_64>>>(buf0, W_enc2, nullptr, buf1);
    k_gather<H, true, true><<<CDIV(N, 16), 256>>>(buf1, b_enc2, buf0);

    // ---- global mean pool + latent projection
    k_pool_acc<<<CDIV(N, 128), 256>>>(batch, buf0);
    k_z<<<1, G * L>>>(W_proj, b_proj, out_z);

    // ---- decoder broadcast
    k_dec_bcast<<<CDIV(N * 16, T), T>>>(batch, W_dproj, b_dproj, buf0);

    // ---- dec0
    k_mmt<H, H, true, false, false><<<MMB, 256, SMT_64_64>>>(buf0, W_dec0, nullptr, buf1);
    k_gather<H, true, true><<<CDIV(N, 16), 256>>>(buf1, b_dec0, buf0);

    // ---- dec1: 64->32 matmul (dinv-scaled), gather at C=32 into d_out
    k_mmt<H, IN, true, false, false><<<MMB, 256, SMT_64_32>>>(buf0, W_dec1, nullptr, buf1);
    k_gather<IN, true, false><<<CDIV(N, 32), 256>>>(buf1, b_dec1, out_recon);
}